// round 1
// baseline (speedup 1.0000x reference)
#include <cuda_runtime.h>
#include <math_constants.h>

// Problem constants (fixed shapes per reference)
#define BATCH 4
#define HDIM 512
#define WDIM 512
#define HW (HDIM * WDIM)          // 262144
#define OFF_CH 18
#define FLOW_CH 8
#define ONUM 9                    // offset pairs
#define FNUM 4                    // flow hypotheses
#define TOTAL_PIX (BATCH * HW)    // 1048576

#define TPB 256
#define NBLOCKS (TOTAL_PIX / TPB) // 4096

__device__ float g_partials[NBLOCKS];

__global__ __launch_bounds__(TPB) void position_loss_main(
    const float* __restrict__ offset,
    const float* __restrict__ flow)
{
    const int t = blockIdx.x * TPB + threadIdx.x;   // one pixel per thread
    const int b = t >> 18;                          // t / HW
    const int p = t & (HW - 1);                     // t % HW

    const float* ob = offset + (size_t)b * OFF_CH * HW + p;
    const float* fb = flow   + (size_t)b * FLOW_CH * HW + p;

    // ---- per-segment (j) precompute: u, v, u*v, 1/(u^2+v^2), min(0,u), max(0,u)
    float fch[FNUM + 1];
    #pragma unroll
    for (int c = 0; c < FNUM + 1; c++)
        fch[c] = fb[c * HW];

    float u[FNUM], v[FNUM], uv[FNUM], rcp[FNUM], lo[FNUM], hi[FNUM];
    #pragma unroll
    for (int j = 0; j < FNUM; j++) {
        u[j]   = fch[j];
        v[j]   = fch[j + 1];
        uv[j]  = u[j] * v[j];
        rcp[j] = __frcp_rn(fmaf(u[j], u[j], v[j] * v[j]));
        lo[j]  = fminf(0.0f, u[j]);
        hi[j]  = fmaxf(0.0f, u[j]);
    }

    // ---- accumulate sum over i of sqrt( min_j candidate^2 )
    float acc = 0.0f;
    #pragma unroll
    for (int i = 0; i < ONUM; i++) {
        const float x  = ob[i * HW];
        const float y  = ob[(i + ONUM) * HW];
        const float xx = x * x;
        const float d1 = fmaf(y, y, xx);            // d1^2

        float s = CUDART_INF_F;
        #pragma unroll
        for (int j = 0; j < FNUM; j++) {
            // x0 = (u*x*x + u*v*y) / (u^2+v^2)
            const float x0 = fmaf(u[j], xx, uv[j] * y) * rcp[j];
            const bool inside = (lo[j] <= x0) & (x0 <= hi[j]);

            // perp^2 = (v*x - u*y)^2 / (u^2+v^2)
            const float cross  = fmaf(v[j], x, -(u[j] * y));
            const float perpsq = (cross * cross) * rcp[j];

            // end^2 = min(d1^2, d2^2)
            const float dx = x - u[j];
            const float dy = y - v[j];
            const float d2 = fmaf(dx, dx, dy * dy);
            const float endsq = fminf(d1, d2);

            const float cand = inside ? perpsq : endsq;
            s = fminf(s, cand);
        }
        acc += sqrtf(s);
    }

    // ---- block reduction (deterministic within block)
    __shared__ float sm[TPB / 32];
    #pragma unroll
    for (int o = 16; o > 0; o >>= 1)
        acc += __shfl_down_sync(0xFFFFFFFFu, acc, o);
    const int lane = threadIdx.x & 31;
    const int warp = threadIdx.x >> 5;
    if (lane == 0) sm[warp] = acc;
    __syncthreads();
    if (warp == 0) {
        float w = (lane < TPB / 32) ? sm[lane] : 0.0f;
        #pragma unroll
        for (int o = 4; o > 0; o >>= 1)
            w += __shfl_down_sync(0xFFFFFFFFu, w, o);
        if (lane == 0) g_partials[blockIdx.x] = w;
    }
}

__global__ __launch_bounds__(TPB) void position_loss_finalize(float* __restrict__ out)
{
    // Deterministic fixed-tree sum of NBLOCKS partials with one block.
    float acc = 0.0f;
    for (int i = threadIdx.x; i < NBLOCKS; i += TPB)
        acc += g_partials[i];

    __shared__ float sm[TPB / 32];
    #pragma unroll
    for (int o = 16; o > 0; o >>= 1)
        acc += __shfl_down_sync(0xFFFFFFFFu, acc, o);
    const int lane = threadIdx.x & 31;
    const int warp = threadIdx.x >> 5;
    if (lane == 0) sm[warp] = acc;
    __syncthreads();
    if (warp == 0) {
        float w = (lane < TPB / 32) ? sm[lane] : 0.0f;
        #pragma unroll
        for (int o = 4; o > 0; o >>= 1)
            w += __shfl_down_sync(0xFFFFFFFFu, w, o);
        if (lane == 0)
            out[0] = w * (1.0f / ((float)ONUM * (float)HW));
    }
}

extern "C" void kernel_launch(void* const* d_in, const int* in_sizes, int n_in,
                              void* d_out, int out_size)
{
    const float* offset = (const float*)d_in[0];
    const float* flow   = (const float*)d_in[1];
    float* out = (float*)d_out;

    position_loss_main<<<NBLOCKS, TPB>>>(offset, flow);
    position_loss_finalize<<<1, TPB>>>(out);
}

// round 13
// speedup vs baseline: 1.2056x; 1.2056x over previous
#include <cuda_runtime.h>
#include <math_constants.h>

// Problem constants (fixed shapes per reference)
#define BATCH 4
#define HDIM 512
#define WDIM 512
#define HW (HDIM * WDIM)          // 262144
#define OFF_CH 18
#define FLOW_CH 8
#define ONUM 9                    // offset pairs
#define FNUM 4                    // flow hypotheses
#define TOTAL_PIX (BATCH * HW)    // 1048576
#define PIX_PER_THREAD 2

#define TPB 256
#define NBLOCKS (TOTAL_PIX / (TPB * PIX_PER_THREAD)) // 2048

__device__ float        g_partials[NBLOCKS];
__device__ unsigned int g_count = 0;

__device__ __forceinline__ float block_reduce(float acc, float* sm)
{
    const int lane = threadIdx.x & 31;
    const int warp = threadIdx.x >> 5;
    #pragma unroll
    for (int o = 16; o > 0; o >>= 1)
        acc += __shfl_down_sync(0xFFFFFFFFu, acc, o);
    if (lane == 0) sm[warp] = acc;
    __syncthreads();
    if (warp == 0) {
        float w = (lane < TPB / 32) ? sm[lane] : 0.0f;
        #pragma unroll
        for (int o = 4; o > 0; o >>= 1)
            w += __shfl_down_sync(0xFFFFFFFFu, w, o);
        return w;   // valid in lane 0
    }
    return 0.0f;
}

__global__ __launch_bounds__(TPB) void position_loss_fused(
    const float* __restrict__ offset,
    const float* __restrict__ flow,
    float* __restrict__ out)
{
    // Each thread handles 2 adjacent pixels (contiguous in w) via float2 loads.
    const int t = blockIdx.x * TPB + threadIdx.x;   // pixel-pair index
    const int b = t >> 17;                          // t / (HW/2)
    const int p = (t & ((HW >> 1) - 1)) * 2;        // even pixel within image

    const float* ob = offset + (size_t)b * OFF_CH * HW + p;
    const float* fb = flow   + (size_t)b * FLOW_CH * HW + p;

    // ---- per-segment (j) precompute for both lanes: u, v, uu+vv, 1/(uu+vv)
    float2 fch[FNUM + 1];
    #pragma unroll
    for (int c = 0; c < FNUM + 1; c++)
        fch[c] = __ldcs((const float2*)&fb[c * HW]);

    float2 u[FNUM], v[FNUM], uuvv[FNUM], rcp[FNUM];
    #pragma unroll
    for (int j = 0; j < FNUM; j++) {
        u[j] = fch[j];
        v[j] = fch[j + 1];
        uuvv[j].x = fmaf(u[j].x, u[j].x, v[j].x * v[j].x);
        uuvv[j].y = fmaf(u[j].y, u[j].y, v[j].y * v[j].y);
        rcp[j].x  = __frcp_rn(uuvv[j].x);
        rcp[j].y  = __frcp_rn(uuvv[j].y);
    }

    // ---- accumulate sum over i of sqrt( clamp0( min_j candidate^2 ) ), 2 lanes
    float acc0 = 0.0f, acc1 = 0.0f;
    #pragma unroll
    for (int i = 0; i < ONUM; i++) {
        const float2 xp = __ldcs((const float2*)&ob[i * HW]);
        const float2 yp = __ldcs((const float2*)&ob[(i + ONUM) * HW]);

        const float xx0 = xp.x * xp.x,              xx1 = xp.y * xp.y;
        const float d10 = fmaf(yp.x, yp.x, xx0),    d11 = fmaf(yp.y, yp.y, xx1);

        float s0 = CUDART_INF_F, s1 = CUDART_INF_F;
        #pragma unroll
        for (int j = 0; j < FNUM; j++) {
            // lane 0
            {
                const float tt = fmaf(v[j].x, yp.x, xx0);
                const bool inside = (tt >= 0.0f) & (tt <= uuvv[j].x);
                const float dot = fmaf(u[j].x, xp.x, v[j].x * yp.x);
                const float m      = dot * rcp[j].x;
                const float perpsq = fmaf(-m, dot, d10);
                const float d2 = fmaf(-2.0f, dot, d10) + uuvv[j].x;
                const float endsq = fminf(d10, d2);
                s0 = fminf(s0, inside ? perpsq : endsq);
            }
            // lane 1
            {
                const float tt = fmaf(v[j].y, yp.y, xx1);
                const bool inside = (tt >= 0.0f) & (tt <= uuvv[j].y);
                const float dot = fmaf(u[j].y, xp.y, v[j].y * yp.y);
                const float m      = dot * rcp[j].y;
                const float perpsq = fmaf(-m, dot, d11);
                const float d2 = fmaf(-2.0f, dot, d11) + uuvv[j].y;
                const float endsq = fminf(d11, d2);
                s1 = fminf(s1, inside ? perpsq : endsq);
            }
        }
        acc0 += sqrtf(fmaxf(s0, 0.0f));
        acc1 += sqrtf(fmaxf(s1, 0.0f));
    }
    float acc = acc0 + acc1;

    // ---- block reduction + partial store
    __shared__ float sm[TPB / 32];
    float blocksum = block_reduce(acc, sm);
    if (threadIdx.x == 0)
        g_partials[blockIdx.x] = blocksum;

    // ---- last-block finalize (deterministic fixed-order tree)
    __shared__ bool is_last;
    __threadfence();
    if (threadIdx.x == 0) {
        unsigned int prev = atomicAdd(&g_count, 1u);
        is_last = (prev == (unsigned int)(NBLOCKS - 1));
    }
    __syncthreads();

    if (is_last) {
        float a = 0.0f;
        #pragma unroll
        for (int k = 0; k < NBLOCKS / TPB; k++)
            a += __ldcg(&g_partials[threadIdx.x + k * TPB]);
        __syncthreads();  // reuse of sm[]
        float total = block_reduce(a, sm);
        if (threadIdx.x == 0) {
            out[0] = total * (1.0f / ((float)ONUM * (float)HW));
            g_count = 0;   // reset for next launch / graph replay
        }
    }
}

extern "C" void kernel_launch(void* const* d_in, const int* in_sizes, int n_in,
                              void* d_out, int out_size)
{
    const float* offset = (const float*)d_in[0];
    const float* flow   = (const float*)d_in[1];
    float* out = (float*)d_out;

    position_loss_fused<<<NBLOCKS, TPB>>>(offset, flow, out);
}